// round 3
// baseline (speedup 1.0000x reference)
#include <cuda_runtime.h>
#include <cstdint>

// Haar DWT2 on x:[8,64,512,512] f32 -> 4 subbands [8,64,256,256] packed
// subband-major into d_out (LL, LH, HL, HH).
//
// Round 2: 8 output columns per thread.
//   reads  2x float4 from input row 2i, 2x float4 from row 2i+1  (64 B, __ldcs)
//   writes 1x float4 to each of 4 subbands                        (64 B, __stcs)
// Streaming hints: zero data reuse, keep L2 from retaining dead lines.

static constexpr int W_IN = 512;
static constexpr int H_OUT = 256;
static constexpr int W_OUT = 256;
static constexpr int QUADS_PER_ROW = W_OUT / 4;                  // 64 threads per output row
static constexpr long long PLANE_IN  = (long long)W_IN * W_IN;   // 262144
static constexpr long long PLANE_OUT = (long long)H_OUT * W_OUT; // 65536
static constexpr long long SUBBAND_STRIDE = 512LL * PLANE_OUT;   // 33,554,432

__device__ __forceinline__ void haar_pair(float a, float b, float c, float d,
                                          float& ll, float& lh, float& hl, float& hh)
{
    const float apb = a + b, amb = a - b;
    const float cpd = c + d, cmd = c - d;
    ll = (apb + cpd) * 0.5f;
    lh = (apb - cpd) * 0.5f;
    hl = (amb + cmd) * 0.5f;
    hh = (amb - cmd) * 0.5f;
}

__global__ void __launch_bounds__(256)
haar_dwt2_kernel(const float* __restrict__ x, float* __restrict__ out)
{
    const unsigned tid = blockIdx.x * blockDim.x + threadIdx.x;
    // tid layout: [plane p : 512][out-row i : 256][col-quad j : 64]
    const unsigned j = tid & (QUADS_PER_ROW - 1);        // 0..63  (4 out cols = 8 in cols)
    const unsigned i = (tid >> 6) & (H_OUT - 1);         // 0..255
    const unsigned p = tid >> 14;                        // 0..511

    const float4* row0 = (const float4*)(x + (long long)p * PLANE_IN
                                           + (long long)(2u * i) * W_IN) + 2u * j;
    const float4* row1 = row0 + (W_IN / 4);

    // Issue all 4 loads up-front (MLP=4, independent).
    const float4 r0a = __ldcs(row0);
    const float4 r0b = __ldcs(row0 + 1);
    const float4 r1a = __ldcs(row1);
    const float4 r1b = __ldcs(row1 + 1);

    float4 ll, lh, hl, hh;
    haar_pair(r0a.x, r0a.y, r1a.x, r1a.y, ll.x, lh.x, hl.x, hh.x);
    haar_pair(r0a.z, r0a.w, r1a.z, r1a.w, ll.y, lh.y, hl.y, hh.y);
    haar_pair(r0b.x, r0b.y, r1b.x, r1b.y, ll.z, lh.z, hl.z, hh.z);
    haar_pair(r0b.z, r0b.w, r1b.z, r1b.w, ll.w, lh.w, hl.w, hh.w);

    const long long obase = (long long)p * PLANE_OUT + (long long)i * W_OUT + 4u * j;
    __stcs((float4*)(out + obase),                      ll);
    __stcs((float4*)(out + obase +     SUBBAND_STRIDE), lh);
    __stcs((float4*)(out + obase + 2 * SUBBAND_STRIDE), hl);
    __stcs((float4*)(out + obase + 3 * SUBBAND_STRIDE), hh);
}

extern "C" void kernel_launch(void* const* d_in, const int* in_sizes, int n_in,
                              void* d_out, int out_size)
{
    const float* x = (const float*)d_in[0];
    float* out = (float*)d_out;

    // total threads = 512 planes * 256 rows * 64 quads = 8,388,608
    const unsigned total = 512u * 256u * 64u;
    const unsigned block = 256u;
    const unsigned grid = total / block; // 32768
    haar_dwt2_kernel<<<grid, block>>>(x, out);
}